// round 15
// baseline (speedup 1.0000x reference)
#include <cuda_runtime.h>
#include <cuda_fp16.h>
#include <cstdint>

#define N_ROWS 4096
#define VOCAB  50000
#define DIM    64

#define BM 128
#define BN 128
#define TPB   391                 // column tiles per row-block
#define MB    32                  // row blocks
#define TOTAL (TPB * MB)          // 12512
#define GRID_P 444                // 3 CTAs/SM x 148 SMs
#define LOSS_BLOCKS 16

#define ROWB 144                  // bytes per smem tile row (72 halves, conflict-free)
#define A_SM_BYTES (BM * ROWB)    // 18432
#define SMEM_TOTAL (3 * A_SM_BYTES)   // A + B double buffer = 55296 (x3 CTAs = 162KB/SM)

#define LOG2E 1.4426950408889634f

// scratch (no allocs allowed -> device globals)
__device__ float  g_sums[N_ROWS];
__device__ float  g_loss;
__device__ int    g_loss_cnt;
__device__ __half g_A16[N_ROWS * DIM];   // pre-scaled by log2e
__device__ __half g_B16[VOCAB * DIM];

__device__ __forceinline__ uint32_t smem_u32(const void* p) {
    uint32_t a;
    asm("{ .reg .u64 t; cvta.to.shared.u64 t, %1; cvt.u32.u64 %0, t; }" : "=r"(a) : "l"(p));
    return a;
}
__device__ __forceinline__ float ex2f(float x) {      // exp(logit): logits log2-domain
    float y;
    asm("ex2.approx.f32 %0, %1;" : "=f"(y) : "f"(x));
    return y;
}
// B-tile column permutation: MMA-space row q = nf*8+lc*2+j holds natural column
// (nf&2)*8 + lc*4 + (nf&1)*2 + j  -> pass-1 stores are full STG.128.
__device__ __forceinline__ int permB(int r) {
    int q = r & 31;
    int nf = q >> 3, lc = (q >> 1) & 3, j = q & 1;
    return (r & ~31) | ((nf & 2) << 3) | (lc << 2) | ((nf & 1) << 1) | j;
}
#define CP_ASYNC16(dst, src, sz) \
    asm volatile("cp.async.cg.shared.global [%0], [%1], 16, %2;" :: "r"(dst), "l"(src), "r"(sz))
#define CP_COMMIT()  asm volatile("cp.async.commit_group;" ::: "memory")
#define CP_WAIT0()   asm volatile("cp.async.wait_group 0;" ::: "memory")
#define LDMATRIX_X4(r0, r1, r2, r3, addr) \
    asm volatile("ldmatrix.sync.aligned.m8n8.x4.shared.b16 {%0,%1,%2,%3}, [%4];" \
                 : "=r"(r0), "=r"(r1), "=r"(r2), "=r"(r3) : "r"(addr))

// init + fp32 -> fp16 convert. A is pre-scaled by log2e so exp(logit) == ex2(gemm_out).
__global__ void convert_kernel(const float* __restrict__ A, const float* __restrict__ B) {
    int i = blockIdx.x * blockDim.x + threadIdx.x;               // float4 index
    if (i < N_ROWS) g_sums[i] = 0.f;
    if (i == 0) { g_loss = 0.f; g_loss_cnt = 0; }
    const int nA4 = N_ROWS * DIM / 4;
    const int nB4 = VOCAB * DIM / 4;
    if (i < nA4) {
        float4 v = ((const float4*)A)[i];
        __half2* d = (__half2*)g_A16;
        d[i * 2 + 0] = __floats2half2_rn(v.x * LOG2E, v.y * LOG2E);
        d[i * 2 + 1] = __floats2half2_rn(v.z * LOG2E, v.w * LOG2E);
    }
    int j = i - nA4;
    if (j >= 0 && j < nB4) {
        float4 v = ((const float4*)B)[j];
        __half2* d = (__half2*)g_B16;
        d[j * 2 + 0] = __floats2half2_rn(v.x, v.y);
        d[j * 2 + 1] = __floats2half2_rn(v.z, v.w);
    }
}

// Persistent strip kernel; contiguous tiles per CTA; cp.async double-buffered B.
// mf-major slabs: per 16-row slab -> 16 MMAs (A-frag LDSM pipelined one step
// ahead) then that slab's epilogue, interleaving stores/exp with tensor work.
// PASS 0: logits -> ex2 (f16x2) -> row-sum register accum -> atomic flush per m.
// PASS 1: loss (blocks 0..15) then logits -> ex2 * (1/sum) -> STG.128 streaming.
template <int PASS>
__global__ void __launch_bounds__(256, 3)
gemm_softmax_kernel(float* __restrict__ out,
                    const int* __restrict__ label_words,
                    const float* __restrict__ inp,
                    const float* __restrict__ emb,
                    long long lossIdx)
{
    extern __shared__ char smem[];
    __half* As = (__half*)smem;
    const uint32_t sA = smem_u32(smem);
    const uint32_t sB0 = sA + A_SM_BYTES;

    const int tid  = threadIdx.x;
    const int lane = tid & 31;
    const int wid  = tid >> 5;
    const int wm = wid >> 2, wn = wid & 3;
    const int mBase = wm * 64, nBase = wn * 32;
    const int lr = lane >> 2, lc = lane & 3;

    // ldmatrix per-lane base addresses (kk=0, mf/p=0)
    const uint32_t aAddr0 = sA +
        (uint32_t)(mBase + ((lane >> 3) & 1) * 8 + (lane & 7)) * ROWB + (lane >> 4) * 16;
    const uint32_t bOff0 =
        (uint32_t)(nBase + (lane >> 4) * 8 + (lane & 7)) * ROWB + ((lane >> 3) & 1) * 16;

    // balanced contiguous strips; remainder tiles go to HIGH block ids so the
    // loss blocks (0..15) get the short strips
    const int base = TOTAL / GRID_P, rem = TOTAL % GRID_P;
    const int b = blockIdx.x;
    const int cut = GRID_P - rem;
    const int gBeg = b * base + (b > cut ? b - cut : 0);
    const int gEnd = gBeg + base + (b >= cut ? 1 : 0);

    // prologue: prefetch first B tile into buffer 0 (async; overlaps loss below)
    {
        const int v0 = (gBeg % TPB) * BN;
        #pragma unroll
        for (int t = 0; t < 4; t++) {
            int i = tid + t * 256;                 // 16B chunk id, 0..1023
            int row = i >> 3, c8 = i & 7;
            int v = v0 + permB(row);
            uint32_t dst = sB0 + row * ROWB + c8 * 16;
            const __half* src = g_B16 + (size_t)v * DIM + c8 * 8;
            CP_ASYNC16(dst, src, (v < VOCAB) ? 16 : 0);
        }
        CP_COMMIT();
    }

    // ---- fused loss (PASS 1, blocks 0..15): sums are final before this kernel ----
    if (PASS == 1 && b < LOSS_BLOCKS) {
        int n = b * 256 + tid;
        bool is64 = true;                          // int64 labels: odd words all zero
        #pragma unroll
        for (int i = 0; i < 64; i++) is64 &= (label_words[2 * i + 1] == 0);
        int lab = is64 ? label_words[2 * n] : label_words[n];
        const float4* a4 = (const float4*)(inp + (size_t)n * DIM);
        const float4* b4 = (const float4*)(emb + (size_t)lab * DIM);
        float dot = 0.f;
        #pragma unroll
        for (int i = 0; i < DIM / 4; i++) {
            float4 x = a4[i], y = b4[i];
            dot += x.x * y.x + x.y * y.y + x.z * y.z + x.w * y.w;
        }
        float v = logf(g_sums[n]) - dot;
        float* red = (float*)smem;                 // A region; A not loaded yet
        red[tid] = v;
        __syncthreads();
        for (int s = 128; s > 0; s >>= 1) {
            if (tid < s) red[tid] += red[tid + s];
            __syncthreads();
        }
        if (tid == 0) {
            atomicAdd(&g_loss, red[0]);
            __threadfence();
            int c = atomicAdd(&g_loss_cnt, 1);
            if (c == LOSS_BLOCKS - 1)
                out[lossIdx] = atomicAdd(&g_loss, 0.f) * (1.0f / (float)N_ROWS);
        }
    }

    int curM = -1;
    int buf = 0;
    float racc[8];                                 // pass0 row-sum accumulators
    float rinv[8];                                 // pass1 reciprocal sums
    #pragma unroll
    for (int k = 0; k < 8; k++) { racc[k] = 0.f; rinv[k] = 0.f; }

    // ---- one tile, FULL known at compile time; A LDSM pipelined one step ----
    auto do_tile = [&](int v0, int m0, int bufNow, auto fullTag) {
        constexpr bool FULL = decltype(fullTag)::value;
        const uint32_t bAddr0 = sB0 + bufNow * A_SM_BYTES + bOff0;
        unsigned bf[4][4][2];                      // [kk][nf][2]
        #pragma unroll
        for (int kk = 0; kk < 4; kk++)
            #pragma unroll
            for (int p = 0; p < 2; p++)
                LDMATRIX_X4(bf[kk][2 * p][0], bf[kk][2 * p][1],
                            bf[kk][2 * p + 1][0], bf[kk][2 * p + 1][1],
                            bAddr0 + p * (16 * ROWB) + kk * 32);
        unsigned a0, a1, a2, a3;
        LDMATRIX_X4(a0, a1, a2, a3, aAddr0);       // (mf=0, kk=0)
        #pragma unroll
        for (int mf = 0; mf < 4; mf++) {
            float c[4][4];
            #pragma unroll
            for (int nf = 0; nf < 4; nf++)
                #pragma unroll
                for (int d = 0; d < 4; d++) c[nf][d] = 0.f;
            #pragma unroll
            for (int kk = 0; kk < 4; kk++) {
                #pragma unroll
                for (int nf = 0; nf < 4; nf++) {
                    asm volatile(
                        "mma.sync.aligned.m16n8k16.row.col.f32.f16.f16.f32 "
                        "{%0,%1,%2,%3}, {%4,%5,%6,%7}, {%8,%9}, {%0,%1,%2,%3};"
                        : "+f"(c[nf][0]), "+f"(c[nf][1]), "+f"(c[nf][2]), "+f"(c[nf][3])
                        : "r"(a0), "r"(a1), "r"(a2), "r"(a3),
                          "r"(bf[kk][nf][0]), "r"(bf[kk][nf][1]));
                }
                // preload next A frag AFTER its consumers issued (WAR safe; hides LDS lat)
                if (!(mf == 3 && kk == 3)) {
                    int nmf = (kk == 3) ? mf + 1 : mf;
                    int nkk = (kk == 3) ? 0 : kk + 1;
                    LDMATRIX_X4(a0, a1, a2, a3, aAddr0 + nmf * (16 * ROWB) + nkk * 32);
                }
            }
            if (PASS == 0) {
                if (FULL) {
                    #pragma unroll
                    for (int h = 0; h < 2; h++) {
                        __half2 hs = __floats2half2_rn(0.f, 0.f);
                        #pragma unroll
                        for (int nf = 0; nf < 4; nf++) {
                            __half2 p = __floats2half2_rn(c[nf][h * 2 + 0], c[nf][h * 2 + 1]);
                            hs = __hadd2(hs, h2exp2(p));   // ex2.approx.f16x2
                        }
                        float2 f = __half22float2(hs);
                        racc[mf * 2 + h] += f.x + f.y;
                    }
                } else {                           // 32 of 12512 tiles: masked scalar path
                    #pragma unroll
                    for (int h = 0; h < 2; h++) {
                        float s = 0.f;
                        #pragma unroll
                        for (int nf = 0; nf < 4; nf++) {
                            int col = v0 + nBase + (nf >> 1) * 16 + lc * 4 + (nf & 1) * 2;
                            float e0 = ex2f(c[nf][h * 2 + 0]);
                            float e1 = ex2f(c[nf][h * 2 + 1]);
                            s += (col     < VOCAB) ? e0 : 0.f;
                            s += (col + 1 < VOCAB) ? e1 : 0.f;
                        }
                        racc[mf * 2 + h] += s;
                    }
                }
            } else {
                #pragma unroll
                for (int h = 0; h < 2; h++) {
                    const float r = rinv[mf * 2 + h];
                    const int rl = mBase + mf * 16 + h * 8 + lr;
                    float* op = out + (size_t)(m0 + rl) * VOCAB;
                    #pragma unroll
                    for (int gg = 0; gg < 2; gg++) {
                        int col = v0 + nBase + gg * 16 + lc * 4;
                        if (FULL || col < VOCAB) {   // 50000 % 4 == 0 -> no straddle
                            float4 p;
                            p.x = ex2f(c[2 * gg + 0][h * 2 + 0]) * r;
                            p.y = ex2f(c[2 * gg + 0][h * 2 + 1]) * r;
                            p.z = ex2f(c[2 * gg + 1][h * 2 + 0]) * r;
                            p.w = ex2f(c[2 * gg + 1][h * 2 + 1]) * r;
                            __stcs((float4*)(op + col), p);
                        }
                    }
                }
            }
        }
    };

    for (int g = gBeg; g < gEnd; g++) {
        const int m = g / TPB;
        const int v0 = (g % TPB) * BN;
        const int m0 = m * BM;

        if (m != curM) {                           // <=2 times per strip
            __syncthreads();                       // everyone done with old As
            if (PASS == 0 && curM >= 0) {          // flush row sums of previous block
                #pragma unroll
                for (int k = 0; k < 8; k++) {
                    float s = racc[k];
                    s += __shfl_xor_sync(0xffffffffu, s, 1);
                    s += __shfl_xor_sync(0xffffffffu, s, 2);
                    if (lc == 0)
                        atomicAdd(&g_sums[curM * BM + mBase + (k >> 1) * 16 + (k & 1) * 8 + lr], s);
                    racc[k] = 0.f;
                }
            }
            const uint4* Ag = (const uint4*)(g_A16 + (size_t)m0 * DIM);
            #pragma unroll
            for (int t = 0; t < 4; t++) {
                int i = tid + t * 256;
                int row = i >> 3, c8 = i & 7;
                *(uint4*)((char*)As + row * ROWB + c8 * 16) = Ag[i];
            }
            if (PASS == 1) {
                #pragma unroll
                for (int k = 0; k < 8; k++)
                    rinv[k] = 1.0f / __ldcg(&g_sums[m0 + mBase + (k >> 1) * 16 + (k & 1) * 8 + lr]);
            }
            curM = m;
        }

        CP_WAIT0();                                // current B buffer landed
        __syncthreads();

        // prefetch next B tile into the other buffer (overlaps MMA + epilogue)
        if (g + 1 < gEnd) {
            const int vn = ((g + 1) % TPB) * BN;
            const uint32_t sBn = sB0 + (buf ^ 1) * A_SM_BYTES;
            #pragma unroll
            for (int t = 0; t < 4; t++) {
                int i = tid + t * 256;
                int row = i >> 3, c8 = i & 7;
                int v = vn + permB(row);
                uint32_t dst = sBn + row * ROWB + c8 * 16;
                const __half* src = g_B16 + (size_t)v * DIM + c8 * 8;
                CP_ASYNC16(dst, src, (v < VOCAB) ? 16 : 0);
            }
            CP_COMMIT();
        }

        if (v0 + BN <= VOCAB) do_tile(v0, m0, buf, std::integral_constant<bool, true>{});
        else                  do_tile(v0, m0, buf, std::integral_constant<bool, false>{});
        buf ^= 1;
    }

    if (PASS == 0 && curM >= 0) {                  // final flush
        #pragma unroll
        for (int k = 0; k < 8; k++) {
            float s = racc[k];
            s += __shfl_xor_sync(0xffffffffu, s, 1);
            s += __shfl_xor_sync(0xffffffffu, s, 2);
            if (lc == 0)
                atomicAdd(&g_sums[curM * BM + mBase + (k >> 1) * 16 + (k & 1) * 8 + lr], s);
        }
    }
}

extern "C" void kernel_launch(void* const* d_in, const int* in_sizes, int n_in,
                              void* d_out, int out_size) {
    const int*   label = (const int*)d_in[0];      // int32 or int64 (sniffed in-kernel)
    const float* inp   = (const float*)d_in[1];    // [4096, 64]
    const float* emb   = (const float*)d_in[2];    // [50000, 64]
    float* out = (float*)d_out;                    // [4096*50000] probs + [1] loss

    static int attr_done = 0;
    if (!attr_done) {
        cudaFuncSetAttribute(gemm_softmax_kernel<0>,
                             cudaFuncAttributeMaxDynamicSharedMemorySize, SMEM_TOTAL);
        cudaFuncSetAttribute(gemm_softmax_kernel<1>,
                             cudaFuncAttributeMaxDynamicSharedMemorySize, SMEM_TOTAL);
        attr_done = 1;
    }
    long long lossIdx = (long long)out_size - 1;

    convert_kernel<<<(N_ROWS * DIM / 4 + VOCAB * DIM / 4 + 255) / 256, 256>>>(inp, emb);
    gemm_softmax_kernel<0><<<GRID_P, 256, SMEM_TOTAL>>>(out, label, inp, emb, lossIdx);
    gemm_softmax_kernel<1><<<GRID_P, 256, SMEM_TOTAL>>>(out, label, inp, emb, lossIdx);
}

// round 16
// speedup vs baseline: 1.0078x; 1.0078x over previous
#include <cuda_runtime.h>
#include <cuda_fp16.h>
#include <cstdint>

#define N_ROWS 4096
#define VOCAB  50000
#define DIM    64

#define BM 128
#define BN 128
#define TPB   391                 // column tiles per row-block
#define MB    32                  // row blocks
#define TOTAL (TPB * MB)          // 12512
#define GRID_P 444                // 3 CTAs/SM x 148 SMs
#define LOSS_BLOCKS 16

#define ROWB 144                  // bytes per smem tile row (72 halves, conflict-free)
#define A_SM_BYTES (BM * ROWB)    // 18432
#define SMEM_TOTAL (3 * A_SM_BYTES)   // A + B double buffer = 55296 (x3 CTAs = 162KB/SM)

#define LOG2E 1.4426950408889634f

// scratch (no allocs allowed -> device globals)
__device__ float  g_sums[N_ROWS];
__device__ float  g_loss;
__device__ int    g_loss_cnt;
__device__ __half g_A16[N_ROWS * DIM];   // pre-scaled by log2e
__device__ __half g_B16[VOCAB * DIM];

__device__ __forceinline__ uint32_t smem_u32(const void* p) {
    uint32_t a;
    asm("{ .reg .u64 t; cvta.to.shared.u64 t, %1; cvt.u32.u64 %0, t; }" : "=r"(a) : "l"(p));
    return a;
}
__device__ __forceinline__ float ex2f(float x) {      // exp(logit): logits log2-domain
    float y;
    asm("ex2.approx.f32 %0, %1;" : "=f"(y) : "f"(x));
    return y;
}
__device__ __forceinline__ float rcpf(float x) {      // 1/x, 2^-23 rel err (gate is 1e-3)
    float y;
    asm("rcp.approx.f32 %0, %1;" : "=f"(y) : "f"(x));
    return y;
}
// B-tile column permutation: MMA-space row q = nf*8+lc*2+j holds natural column
// (nf&2)*8 + lc*4 + (nf&1)*2 + j  -> pass-1 stores are full STG.128.
__device__ __forceinline__ int permB(int r) {
    int q = r & 31;
    int nf = q >> 3, lc = (q >> 1) & 3, j = q & 1;
    return (r & ~31) | ((nf & 2) << 3) | (lc << 2) | ((nf & 1) << 1) | j;
}
#define CP_ASYNC16(dst, src, sz) \
    asm volatile("cp.async.cg.shared.global [%0], [%1], 16, %2;" :: "r"(dst), "l"(src), "r"(sz))
#define CP_COMMIT()  asm volatile("cp.async.commit_group;" ::: "memory")
#define CP_WAIT0()   asm volatile("cp.async.wait_group 0;" ::: "memory")
#define LDMATRIX_X4(r0, r1, r2, r3, addr) \
    asm volatile("ldmatrix.sync.aligned.m8n8.x4.shared.b16 {%0,%1,%2,%3}, [%4];" \
                 : "=r"(r0), "=r"(r1), "=r"(r2), "=r"(r3) : "r"(addr))

// init + fp32 -> fp16 convert. A is pre-scaled by log2e so exp(logit) == ex2(gemm_out).
__global__ void convert_kernel(const float* __restrict__ A, const float* __restrict__ B) {
    int i = blockIdx.x * blockDim.x + threadIdx.x;               // float4 index
    if (i < N_ROWS) g_sums[i] = 0.f;
    if (i == 0) { g_loss = 0.f; g_loss_cnt = 0; }
    const int nA4 = N_ROWS * DIM / 4;
    const int nB4 = VOCAB * DIM / 4;
    if (i < nA4) {
        float4 v = ((const float4*)A)[i];
        __half2* d = (__half2*)g_A16;
        d[i * 2 + 0] = __floats2half2_rn(v.x * LOG2E, v.y * LOG2E);
        d[i * 2 + 1] = __floats2half2_rn(v.z * LOG2E, v.w * LOG2E);
    }
    int j = i - nA4;
    if (j >= 0 && j < nB4) {
        float4 v = ((const float4*)B)[j];
        __half2* d = (__half2*)g_B16;
        d[j * 2 + 0] = __floats2half2_rn(v.x, v.y);
        d[j * 2 + 1] = __floats2half2_rn(v.z, v.w);
    }
}

// Persistent strip kernel; contiguous tiles per CTA; cp.async double-buffered B.
// mf-major schedule: per 16-row slab -> 16 MMAs then that slab's epilogue, so
// stores/exp interleave with tensor work inside each warp.
// PASS 0: logits -> ex2 (f16x2) -> row-sum register accum -> atomic flush per m.
// PASS 1: loss (blocks 0..15) then logits -> ex2 * (1/sum) -> STG.128 streaming.
template <int PASS>
__global__ void __launch_bounds__(256, 3)
gemm_softmax_kernel(float* __restrict__ out,
                    const int* __restrict__ label_words,
                    const float* __restrict__ inp,
                    const float* __restrict__ emb,
                    long long lossIdx)
{
    extern __shared__ char smem[];
    __half* As = (__half*)smem;
    const uint32_t sA = smem_u32(smem);
    const uint32_t sB0 = sA + A_SM_BYTES;

    const int tid  = threadIdx.x;
    const int lane = tid & 31;
    const int wid  = tid >> 5;
    const int wm = wid >> 2, wn = wid & 3;
    const int mBase = wm * 64, nBase = wn * 32;
    const int lr = lane >> 2, lc = lane & 3;

    // ldmatrix per-lane base addresses (kk=0, mf/p=0)
    const uint32_t aAddr0 = sA +
        (uint32_t)(mBase + ((lane >> 3) & 1) * 8 + (lane & 7)) * ROWB + (lane >> 4) * 16;
    const uint32_t bOff0 =
        (uint32_t)(nBase + (lane >> 4) * 8 + (lane & 7)) * ROWB + ((lane >> 3) & 1) * 16;

    // balanced contiguous strips; remainder tiles go to HIGH block ids so the
    // loss blocks (0..15) get the short strips
    const int base = TOTAL / GRID_P, rem = TOTAL % GRID_P;
    const int b = blockIdx.x;
    const int cut = GRID_P - rem;
    const int gBeg = b * base + (b > cut ? b - cut : 0);
    const int gEnd = gBeg + base + (b >= cut ? 1 : 0);

    // prologue: prefetch first B tile into buffer 0 (async; overlaps loss below)
    {
        const int v0 = (gBeg % TPB) * BN;
        #pragma unroll
        for (int t = 0; t < 4; t++) {
            int i = tid + t * 256;                 // 16B chunk id, 0..1023
            int row = i >> 3, c8 = i & 7;
            int v = v0 + permB(row);
            uint32_t dst = sB0 + row * ROWB + c8 * 16;
            const __half* src = g_B16 + (size_t)v * DIM + c8 * 8;
            CP_ASYNC16(dst, src, (v < VOCAB) ? 16 : 0);
        }
        CP_COMMIT();
    }

    // ---- fused loss (PASS 1, blocks 0..15): sums are final before this kernel ----
    if (PASS == 1 && b < LOSS_BLOCKS) {
        int n = b * 256 + tid;
        bool is64 = true;                          // int64 labels: odd words all zero
        #pragma unroll
        for (int i = 0; i < 64; i++) is64 &= (label_words[2 * i + 1] == 0);
        int lab = is64 ? label_words[2 * n] : label_words[n];
        const float4* a4 = (const float4*)(inp + (size_t)n * DIM);
        const float4* b4 = (const float4*)(emb + (size_t)lab * DIM);
        float dot = 0.f;
        #pragma unroll
        for (int i = 0; i < DIM / 4; i++) {
            float4 x = a4[i], y = b4[i];
            dot += x.x * y.x + x.y * y.y + x.z * y.z + x.w * y.w;
        }
        float v = logf(g_sums[n]) - dot;
        float* red = (float*)smem;                 // A region; A not loaded yet
        red[tid] = v;
        __syncthreads();
        for (int s = 128; s > 0; s >>= 1) {
            if (tid < s) red[tid] += red[tid + s];
            __syncthreads();
        }
        if (tid == 0) {
            atomicAdd(&g_loss, red[0]);
            __threadfence();
            int c = atomicAdd(&g_loss_cnt, 1);
            if (c == LOSS_BLOCKS - 1)
                out[lossIdx] = atomicAdd(&g_loss, 0.f) * (1.0f / (float)N_ROWS);
        }
    }

    int curM = -1;
    int buf = 0;
    float racc[8];                                 // pass0 row-sum accumulators
    float rinv[8];                                 // pass1 reciprocal sums
    #pragma unroll
    for (int k = 0; k < 8; k++) { racc[k] = 0.f; rinv[k] = 0.f; }

    for (int g = gBeg; g < gEnd; g++) {
        const int m = g / TPB;
        const int v0 = (g % TPB) * BN;
        const int m0 = m * BM;

        if (m != curM) {                           // <=2 times per strip
            __syncthreads();                       // everyone done with old As
            if (PASS == 0 && curM >= 0) {          // flush row sums of previous block
                #pragma unroll
                for (int k = 0; k < 8; k++) {
                    float s = racc[k];
                    s += __shfl_xor_sync(0xffffffffu, s, 1);
                    s += __shfl_xor_sync(0xffffffffu, s, 2);
                    if (lc == 0)
                        atomicAdd(&g_sums[curM * BM + mBase + (k >> 1) * 16 + (k & 1) * 8 + lr], s);
                    racc[k] = 0.f;
                }
            }
            const uint4* Ag = (const uint4*)(g_A16 + (size_t)m0 * DIM);
            #pragma unroll
            for (int t = 0; t < 4; t++) {
                int i = tid + t * 256;
                int row = i >> 3, c8 = i & 7;
                *(uint4*)((char*)As + row * ROWB + c8 * 16) = Ag[i];
            }
            if (PASS == 1) {
                #pragma unroll
                for (int k = 0; k < 8; k++)
                    rinv[k] = rcpf(__ldcg(&g_sums[m0 + mBase + (k >> 1) * 16 + (k & 1) * 8 + lr]));
            }
            curM = m;
        }

        CP_WAIT0();                                // current B buffer landed
        __syncthreads();

        // prefetch next B tile into the other buffer (overlaps MMA + epilogue)
        if (g + 1 < gEnd) {
            const int vn = ((g + 1) % TPB) * BN;
            const uint32_t sBn = sB0 + (buf ^ 1) * A_SM_BYTES;
            #pragma unroll
            for (int t = 0; t < 4; t++) {
                int i = tid + t * 256;
                int row = i >> 3, c8 = i & 7;
                int v = vn + permB(row);
                uint32_t dst = sBn + row * ROWB + c8 * 16;
                const __half* src = g_B16 + (size_t)v * DIM + c8 * 8;
                CP_ASYNC16(dst, src, (v < VOCAB) ? 16 : 0);
            }
            CP_COMMIT();
        }

        // ---- preload ALL B fragments (32 regs), then mf-major slabs ----
        const uint32_t bAddr0 = sB0 + buf * A_SM_BYTES + bOff0;
        unsigned bf[4][4][2];                      // [kk][nf][2]
        #pragma unroll
        for (int kk = 0; kk < 4; kk++)
            #pragma unroll
            for (int p = 0; p < 2; p++)
                LDMATRIX_X4(bf[kk][2 * p][0], bf[kk][2 * p][1],
                            bf[kk][2 * p + 1][0], bf[kk][2 * p + 1][1],
                            bAddr0 + p * (16 * ROWB) + kk * 32);

        const bool full = (v0 + BN <= VOCAB);
        #pragma unroll
        for (int mf = 0; mf < 4; mf++) {
            float c[4][4];
            #pragma unroll
            for (int nf = 0; nf < 4; nf++)
                #pragma unroll
                for (int d = 0; d < 4; d++) c[nf][d] = 0.f;
            #pragma unroll
            for (int kk = 0; kk < 4; kk++) {
                unsigned a0, a1, a2, a3;
                LDMATRIX_X4(a0, a1, a2, a3, aAddr0 + mf * (16 * ROWB) + kk * 32);
                #pragma unroll
                for (int nf = 0; nf < 4; nf++) {
                    asm volatile(
                        "mma.sync.aligned.m16n8k16.row.col.f32.f16.f16.f32 "
                        "{%0,%1,%2,%3}, {%4,%5,%6,%7}, {%8,%9}, {%0,%1,%2,%3};"
                        : "+f"(c[nf][0]), "+f"(c[nf][1]), "+f"(c[nf][2]), "+f"(c[nf][3])
                        : "r"(a0), "r"(a1), "r"(a2), "r"(a3),
                          "r"(bf[kk][nf][0]), "r"(bf[kk][nf][1]));
                }
            }
            // ---- slab epilogue (interleaves with next slab's MMAs) ----
            if (PASS == 0) {
                if (full) {
                    #pragma unroll
                    for (int h = 0; h < 2; h++) {
                        __half2 hs = __floats2half2_rn(0.f, 0.f);
                        #pragma unroll
                        for (int nf = 0; nf < 4; nf++) {
                            __half2 p = __floats2half2_rn(c[nf][h * 2 + 0], c[nf][h * 2 + 1]);
                            hs = __hadd2(hs, h2exp2(p));   // ex2.approx.f16x2
                        }
                        float2 f = __half22float2(hs);
                        racc[mf * 2 + h] += f.x + f.y;
                    }
                } else {                           // 32 of 12512 tiles: masked scalar path
                    #pragma unroll
                    for (int h = 0; h < 2; h++) {
                        float s = 0.f;
                        #pragma unroll
                        for (int nf = 0; nf < 4; nf++) {
                            int col = v0 + nBase + (nf >> 1) * 16 + lc * 4 + (nf & 1) * 2;
                            float e0 = ex2f(c[nf][h * 2 + 0]);
                            float e1 = ex2f(c[nf][h * 2 + 1]);
                            s += (col     < VOCAB) ? e0 : 0.f;
                            s += (col + 1 < VOCAB) ? e1 : 0.f;
                        }
                        racc[mf * 2 + h] += s;
                    }
                }
            } else {
                #pragma unroll
                for (int h = 0; h < 2; h++) {
                    const float r = rinv[mf * 2 + h];
                    const int rl = mBase + mf * 16 + h * 8 + lr;
                    float* op = out + (size_t)(m0 + rl) * VOCAB;
                    #pragma unroll
                    for (int gg = 0; gg < 2; gg++) {
                        int col = v0 + nBase + gg * 16 + lc * 4;
                        if (full || col < VOCAB) {   // 50000 % 4 == 0 -> no straddle
                            float4 p;
                            p.x = ex2f(c[2 * gg + 0][h * 2 + 0]) * r;
                            p.y = ex2f(c[2 * gg + 0][h * 2 + 1]) * r;
                            p.z = ex2f(c[2 * gg + 1][h * 2 + 0]) * r;
                            p.w = ex2f(c[2 * gg + 1][h * 2 + 1]) * r;
                            __stcs((float4*)(op + col), p);
                        }
                    }
                }
            }
        }
        buf ^= 1;
    }

    if (PASS == 0 && curM >= 0) {                  // final flush
        #pragma unroll
        for (int k = 0; k < 8; k++) {
            float s = racc[k];
            s += __shfl_xor_sync(0xffffffffu, s, 1);
            s += __shfl_xor_sync(0xffffffffu, s, 2);
            if (lc == 0)
                atomicAdd(&g_sums[curM * BM + mBase + (k >> 1) * 16 + (k & 1) * 8 + lr], s);
        }
    }
}

extern "C" void kernel_launch(void* const* d_in, const int* in_sizes, int n_in,
                              void* d_out, int out_size) {
    const int*   label = (const int*)d_in[0];      // int32 or int64 (sniffed in-kernel)
    const float* inp   = (const float*)d_in[1];    // [4096, 64]
    const float* emb   = (const float*)d_in[2];    // [50000, 64]
    float* out = (float*)d_out;                    // [4096*50000] probs + [1] loss

    static int attr_done = 0;
    if (!attr_done) {
        cudaFuncSetAttribute(gemm_softmax_kernel<0>,
                             cudaFuncAttributeMaxDynamicSharedMemorySize, SMEM_TOTAL);
        cudaFuncSetAttribute(gemm_softmax_kernel<1>,
                             cudaFuncAttributeMaxDynamicSharedMemorySize, SMEM_TOTAL);
        attr_done = 1;
    }
    long long lossIdx = (long long)out_size - 1;

    convert_kernel<<<(N_ROWS * DIM / 4 + VOCAB * DIM / 4 + 255) / 256, 256>>>(inp, emb);
    gemm_softmax_kernel<0><<<GRID_P, 256, SMEM_TOTAL>>>(out, label, inp, emb, lossIdx);
    gemm_softmax_kernel<1><<<GRID_P, 256, SMEM_TOTAL>>>(out, label, inp, emb, lossIdx);
}